// round 8
// baseline (speedup 1.0000x reference)
#include <cuda_runtime.h>
#include <cuda_fp16.h>
#include <stdint.h>

// ---------------- problem constants ----------------
#define TSTEPS 512
#define BSZ    256
#define NIN    128
#define NHID   512
#define NOUT   10
#define DTc    0.042f
#define GAMc   2.7f
#define EPSc   4.7f

// ---------------- kernel config ----------------
#define NCTA    128          // 8 M-tiles(32) x 16 N-tiles(32)
#define KW      8            // warps; each = m32 x n32, k-slice of 128 (state only)
#define THREADS (KW*32)      // 256
#define JPW     8            // k16-blocks per warp
#define PS      36           // partial-tile row stride (16B-aligned rows)

// ---------------- device scratch ----------------
// fp16 state, R6-proven layout: row-major [256 rows][32 blocks of 16 cols];
// within a block, col-pair p (cols 2p,2p+1) at u32 position perm(p):
//   perm(p) = p<4 ? 2p : 2(p-4)+1   -> consumer lane c LDG.64 reads pairs {c, 4+c}
__device__ unsigned g_Hz[2][BSZ*256];
__device__ unsigned g_Hy[2][BSZ*256];
__device__ float    g_preX[(size_t)NCTA*TSTEPS*32*32];  // x@Wx + bias, per-CTA patches
__device__ float    g_hyf[BSZ*NHID];                    // final hy (fp32)
__device__ unsigned g_flag[8][16];                      // per (mi, ni) monotonic step flags
__device__ unsigned g_fin[8];                           // final per-mi arrival counters

// ---------------- helpers ----------------
__device__ __forceinline__ float fast_tanh(float v) {
    float e = __expf(2.0f * v);
    return 1.0f - __fdividef(2.0f, e + 1.0f);
}
__device__ __forceinline__ unsigned pack_h2(float lo, float hi) {
    __half2 h = __floats2half2_rn(lo, hi);
    return *reinterpret_cast<unsigned*>(&h);
}
__device__ __forceinline__ void mma_f16(float* d,
                                        unsigned a0, unsigned a1, unsigned a2, unsigned a3,
                                        unsigned b0, unsigned b1) {
    asm volatile("mma.sync.aligned.m16n8k16.row.col.f32.f16.f16.f32 "
                 "{%0,%1,%2,%3}, {%4,%5,%6,%7}, {%8,%9}, {%0,%1,%2,%3};"
                 : "+f"(d[0]), "+f"(d[1]), "+f"(d[2]), "+f"(d[3])
                 : "r"(a0), "r"(a1), "r"(a2), "r"(a3), "r"(b0), "r"(b1));
}
__device__ __forceinline__ void st_release(unsigned* p, unsigned v) {
    asm volatile("st.release.gpu.global.u32 [%0], %1;" :: "l"(p), "r"(v) : "memory");
}
__device__ __forceinline__ unsigned ld_acq(const unsigned* p) {
    unsigned v;
    asm volatile("ld.acquire.gpu.global.u32 %0, [%1];" : "=r"(v) : "l"(p) : "memory");
    return v;
}
// poll 4 consecutive flags until all >= tgt (acquire loads; cannot be hoisted)
__device__ __forceinline__ void poll4(const unsigned* p, unsigned tgt) {
    unsigned a, b, c, d;
    do {
        a = ld_acq(p);
        b = ld_acq(p + 1);
        c = ld_acq(p + 2);
        d = ld_acq(p + 3);
    } while (a < tgt || b < tgt || c < tgt || d < tgt);
}
__device__ __forceinline__ float2 ldcg2(const float* p) {
    return __ldcg(reinterpret_cast<const float2*>(p));
}

// ---------------- single persistent kernel ----------------
__global__ void __launch_bounds__(THREADS, 1)
cornn_persist(const float* __restrict__ x, const float* __restrict__ W,
              const float* __restrict__ bias,
              const float* __restrict__ Wout, const float* __restrict__ bout,
              float* __restrict__ out) {
    __shared__ float Part[KW * 32 * PS];

    const int tid  = threadIdx.x;
    const int cta  = blockIdx.x;
    const int mi   = cta >> 4;            // 0..7
    const int ni   = cta & 15;            // 0..15
    const int lane = tid & 31;
    const int warp = tid >> 5;            // 0..7

    const int rr   = lane >> 2;
    const int cc   = 2 * (lane & 3);

    // ================= phase 1: preX[t] = x_t @ W[0:128] + b (per-CTA patches) =================
    {
        unsigned xb0[JPW][4], xb1[JPW][4];
        const int n = ni * 32 + rr;
#pragma unroll
        for (int j = 0; j < JPW; ++j) {
            const int k0 = j * 16 + cc;
#pragma unroll
            for (int nf = 0; nf < 4; ++nf) {
                const float* wp = W + (size_t)k0 * NHID + n + nf * 8;
                xb0[j][nf] = pack_h2(wp[0],        wp[NHID]);
                xb1[j][nf] = pack_h2(wp[8 * NHID], wp[9 * NHID]);
            }
        }
        float bc[4][2];
#pragma unroll
        for (int nf = 0; nf < 4; ++nf) {
            int col = ni * 32 + nf * 8 + cc;
            bc[nf][0] = bias[col];
            bc[nf][1] = bias[col + 1];
        }
        const int arow = mi * 32 + rr;
        for (int i = 0; i < TSTEPS / KW; ++i) {
            const int t = warp + KW * i;
            float acc0[4][4], acc1[4][4];
#pragma unroll
            for (int nf = 0; nf < 4; ++nf) {
                acc0[nf][0] = bc[nf][0]; acc0[nf][1] = bc[nf][1];
                acc0[nf][2] = bc[nf][0]; acc0[nf][3] = bc[nf][1];
                acc1[nf][0] = bc[nf][0]; acc1[nf][1] = bc[nf][1];
                acc1[nf][2] = bc[nf][0]; acc1[nf][3] = bc[nf][1];
            }
            const float* rx = x + ((size_t)t * BSZ + arow) * NIN + cc;
#pragma unroll
            for (int j = 0; j < JPW; ++j) {
                float2 v0l = ldcg2(rx + j * 16),            v0h = ldcg2(rx + j * 16 + 8);
                float2 v1l = ldcg2(rx + 8 * NIN + j * 16),  v1h = ldcg2(rx + 8 * NIN + j * 16 + 8);
                float2 v2l = ldcg2(rx + 16 * NIN + j * 16), v2h = ldcg2(rx + 16 * NIN + j * 16 + 8);
                float2 v3l = ldcg2(rx + 24 * NIN + j * 16), v3h = ldcg2(rx + 24 * NIN + j * 16 + 8);
                unsigned a0l = pack_h2(v0l.x, v0l.y), a0h = pack_h2(v0h.x, v0h.y);
                unsigned a1l = pack_h2(v1l.x, v1l.y), a1h = pack_h2(v1h.x, v1h.y);
                unsigned a2l = pack_h2(v2l.x, v2l.y), a2h = pack_h2(v2h.x, v2h.y);
                unsigned a3l = pack_h2(v3l.x, v3l.y), a3h = pack_h2(v3h.x, v3h.y);
#pragma unroll
                for (int nf = 0; nf < 4; ++nf) {
                    mma_f16(acc0[nf], a0l, a1l, a0h, a1h, xb0[j][nf], xb1[j][nf]);
                    mma_f16(acc1[nf], a2l, a3l, a2h, a3h, xb0[j][nf], xb1[j][nf]);
                }
            }
            float* dst = g_preX + ((size_t)(cta * TSTEPS + t) * 32) * 32;
#pragma unroll
            for (int nf = 0; nf < 4; ++nf) {
                int co = nf * 8 + cc;
                __stcg((float2*)(dst + rr * 32 + co),        make_float2(acc0[nf][0], acc0[nf][1]));
                __stcg((float2*)(dst + (rr + 8) * 32 + co),  make_float2(acc0[nf][2], acc0[nf][3]));
                __stcg((float2*)(dst + (rr + 16) * 32 + co), make_float2(acc1[nf][0], acc1[nf][1]));
                __stcg((float2*)(dst + (rr + 24) * 32 + co), make_float2(acc1[nf][2], acc1[nf][3]));
            }
        }
    }

    // ================= init: zero fp16 state (buffer 0), publish flag=1 =================
    const int srow = tid >> 3;                 // 0..31
    const int scol = (tid & 7) * 4;            // 0,4,..,28
    const int grow = mi * 32 + srow;
    const int gcol = ni * 32 + scol;
    const int blk  = gcol >> 4;
    const int pp   = (gcol & 15) >> 1;         // 0,2,4,6
    const int pos0 = (pp < 4) ? 2 * pp : 2 * pp - 7;
    const int pos1 = ((pp + 1) < 4) ? 2 * (pp + 1) : 2 * (pp + 1) - 7;
    const int hbase = grow * 256 + blk * 8;

    __stcg(&g_Hz[0][hbase + pos0], 0u);  __stcg(&g_Hz[0][hbase + pos1], 0u);
    __stcg(&g_Hy[0][hbase + pos0], 0u);  __stcg(&g_Hy[0][hbase + pos1], 0u);
    __syncthreads();
    if (tid == 0) st_release(&g_flag[mi][ni], 1u);

    // ================= main-loop B fragments: W rows 128 + warp*128 .. +128 =================
    unsigned wb0[JPW][4], wb1[JPW][4];
    {
        const int n = ni * 32 + rr;
#pragma unroll
        for (int j = 0; j < JPW; ++j) {
            const int k0 = 128 + warp * 128 + j * 16 + cc;
#pragma unroll
            for (int nf = 0; nf < 4; ++nf) {
                const float* wp = W + (size_t)k0 * NHID + n + nf * 8;
                wb0[j][nf] = pack_h2(wp[0],        wp[NHID]);
                wb1[j][nf] = pack_h2(wp[8 * NHID], wp[9 * NHID]);
            }
        }
    }

    // consumer A-fragment base (R6 layout): slice blocks, lane pair offset 2c
    const int grow0 = mi * 32 + rr;
    const int hoff  = grow0 * 256 + (warp & 3) * 64 + 2 * (lane & 3);

    float hyr[4] = {0, 0, 0, 0}, hzr[4] = {0, 0, 0, 0};

    // ================= recurrence =================
    for (int t = 0; t < TSTEPS; ++t) {
        const int rb = t & 1, wbuf = rb ^ 1;

        // prefetch CTA-private preX patch
        float4 px = __ldcg((const float4*)(g_preX +
                         (((size_t)(cta * TSTEPS + t) * 32 + srow) * 32 + scol)));

        // per-warp poll on exactly the 4 producers of this warp's k-slice
        if (lane == 0) poll4(&g_flag[mi][(warp & 3) * 4], (unsigned)(t + 1));
        __syncwarp();

        const unsigned* hp = ((warp < 4) ? g_Hz[rb] : g_Hy[rb]) + hoff;

        float acc0[4][4], acc1[4][4];
#pragma unroll
        for (int nf = 0; nf < 4; ++nf)
#pragma unroll
            for (int c = 0; c < 4; ++c) { acc0[nf][c] = 0.f; acc1[nf][c] = 0.f; }

#pragma unroll
        for (int j = 0; j < JPW; ++j) {
            const unsigned* q = hp + j * 8;
            uint2 u0 = __ldcg((const uint2*)(q));
            uint2 u1 = __ldcg((const uint2*)(q + 8 * 256));
            uint2 u2 = __ldcg((const uint2*)(q + 16 * 256));
            uint2 u3 = __ldcg((const uint2*)(q + 24 * 256));
#pragma unroll
            for (int nf = 0; nf < 4; ++nf) {
                mma_f16(acc0[nf], u0.x, u1.x, u0.y, u1.y, wb0[j][nf], wb1[j][nf]);
                mma_f16(acc1[nf], u2.x, u3.x, u2.y, u3.y, wb0[j][nf], wb1[j][nf]);
            }
        }

        // write this warp's partial
        {
            float* P = Part + warp * (32 * PS);
#pragma unroll
            for (int nf = 0; nf < 4; ++nf) {
                int co = nf * 8 + cc;
                *(float2*)(P + rr * PS + co)        = make_float2(acc0[nf][0], acc0[nf][1]);
                *(float2*)(P + (rr + 8) * PS + co)  = make_float2(acc0[nf][2], acc0[nf][3]);
                *(float2*)(P + (rr + 16) * PS + co) = make_float2(acc1[nf][0], acc1[nf][1]);
                *(float2*)(P + (rr + 24) * PS + co) = make_float2(acc1[nf][2], acc1[nf][3]);
            }
        }
        __syncthreads();   // all partials in smem

        // reduce 8 partials + preX, tanh, state update, publish fp16 state
        {
            float s0 = px.x, s1 = px.y, s2 = px.z, s3 = px.w;
#pragma unroll
            for (int p = 0; p < KW; ++p) {
                float4 v = *(const float4*)(Part + p * (32 * PS) + srow * PS + scol);
                s0 += v.x; s1 += v.y; s2 += v.z; s3 += v.w;
            }
            float pre0 = fast_tanh(s0);
            float pre1 = fast_tanh(s1);
            float pre2 = fast_tanh(s2);
            float pre3 = fast_tanh(s3);
            hzr[0] += DTc * (pre0 - GAMc * hyr[0] - EPSc * hzr[0]);  hyr[0] += DTc * hzr[0];
            hzr[1] += DTc * (pre1 - GAMc * hyr[1] - EPSc * hzr[1]);  hyr[1] += DTc * hzr[1];
            hzr[2] += DTc * (pre2 - GAMc * hyr[2] - EPSc * hzr[2]);  hyr[2] += DTc * hzr[2];
            hzr[3] += DTc * (pre3 - GAMc * hyr[3] - EPSc * hzr[3]);  hyr[3] += DTc * hzr[3];

            __stcg(&g_Hz[wbuf][hbase + pos0], pack_h2(hzr[0], hzr[1]));
            __stcg(&g_Hz[wbuf][hbase + pos1], pack_h2(hzr[2], hzr[3]));
            __stcg(&g_Hy[wbuf][hbase + pos0], pack_h2(hyr[0], hyr[1]));
            __stcg(&g_Hy[wbuf][hbase + pos1], pack_h2(hyr[2], hyr[3]));
            if (t == TSTEPS - 1) {
                __stcg((float4*)&g_hyf[(size_t)grow * NHID + gcol],
                       make_float4(hyr[0], hyr[1], hyr[2], hyr[3]));
            }
        }
        __syncthreads();   // state stores done CTA-wide; Part reusable
        if (tid == 0) st_release(&g_flag[mi][ni], (unsigned)(t + 2));
    }

    // ================= final wait for all 16 producers of rows mi =================
    if (tid == 0) {
#pragma unroll
        for (int g = 0; g < 4; ++g)
            poll4(&g_flag[mi][g * 4], (unsigned)(TSTEPS + 1));
    }
    __syncthreads();

    // ---- fused output GEMM: out = hy_final @ Wout + bout ----
    if (warp < 2) {
        int row = cta * 2 + warp;
        const float* h = g_hyf + (size_t)row * NHID;
        float acc[NOUT];
#pragma unroll
        for (int o = 0; o < NOUT; ++o) acc[o] = 0.f;
        for (int k = lane; k < NHID; k += 32) {
            float hv = __ldcg(h + k);
#pragma unroll
            for (int o = 0; o < NOUT; ++o) acc[o] += hv * Wout[k * NOUT + o];
        }
#pragma unroll
        for (int o = 0; o < NOUT; ++o) {
#pragma unroll
            for (int s = 16; s > 0; s >>= 1)
                acc[o] += __shfl_xor_sync(0xffffffffu, acc[o], s);
        }
        if (lane == 0) {
#pragma unroll
            for (int o = 0; o < NOUT; ++o) out[row * NOUT + o] = acc[o] + bout[o];
        }
    }
    __syncthreads();

    // ---- self-reset (last arriver per mi group; all pollers of mi already done) ----
    if (tid == 0) {
        unsigned old = atomicAdd(&g_fin[mi], 1u);
        if (old == 15u) {
#pragma unroll
            for (int i = 0; i < 16; ++i) g_flag[mi][i] = 0u;
            __threadfence();
            g_fin[mi] = 0u;
        }
    }
}

// ---------------- launch ----------------
extern "C" void kernel_launch(void* const* d_in, const int* in_sizes, int n_in,
                              void* d_out, int out_size) {
    (void)in_sizes; (void)n_in; (void)out_size;
    const float* x    = (const float*)d_in[0];
    const float* W    = (const float*)d_in[1];
    const float* b    = (const float*)d_in[2];
    const float* Wout = (const float*)d_in[3];
    const float* bout = (const float*)d_in[4];
    float* out = (float*)d_out;

    cornn_persist<<<NCTA, THREADS>>>(x, W, b, Wout, bout, out);
}

// round 9
// speedup vs baseline: 3.5009x; 3.5009x over previous
#include <cuda_runtime.h>
#include <cuda_fp16.h>
#include <stdint.h>

// ---------------- problem constants ----------------
#define TSTEPS 512
#define BSZ    256
#define NIN    128
#define NHID   512
#define NOUT   10
#define DTc    0.042f
#define GAMc   2.7f
#define EPSc   4.7f

// ---------------- kernel config ----------------
#define NCTA    128          // 8 M-tiles(32) x 16 N-tiles(32)
#define KW      8            // warps; each = m32 x n32, k-slice of 128 (state only)
#define THREADS (KW*32)      // 256
#define JPW     8            // k16-blocks per warp
#define PS      36           // partial-tile row stride (16B-aligned rows)

// each (t,mi) counter on its own 256B line (stride 64 u32) to avoid LTS pile-up
#define BARIDX(t, mi) ((((t) * 8) + (mi)) * 64)

// ---------------- device scratch ----------------
// fp16 state, R6-proven layout: row-major [256 rows][32 blocks of 16 cols];
// within a block, col-pair p (cols 2p,2p+1) at u32 position perm(p):
//   perm(p) = p<4 ? 2p : 2(p-4)+1   -> consumer lane c LDG.64 reads pairs {c, 4+c}
__device__ unsigned g_Hz[2][BSZ*256];
__device__ unsigned g_Hy[2][BSZ*256];
__device__ float    g_preX[(size_t)NCTA*TSTEPS*32*32];  // x@Wx + bias, per-CTA patches
__device__ float    g_hyf[BSZ*NHID];                    // final hy (fp32)
__device__ unsigned g_bar[(TSTEPS+1)*8*64];             // padded per-(t,mi) counters
__device__ unsigned g_fin[8];                           // final per-mi arrival counters

// ---------------- helpers ----------------
__device__ __forceinline__ float fast_tanh(float v) {
    float e = __expf(2.0f * v);
    return 1.0f - __fdividef(2.0f, e + 1.0f);
}
__device__ __forceinline__ unsigned pack_h2(float lo, float hi) {
    __half2 h = __floats2half2_rn(lo, hi);
    return *reinterpret_cast<unsigned*>(&h);
}
__device__ __forceinline__ void mma_f16(float* d,
                                        unsigned a0, unsigned a1, unsigned a2, unsigned a3,
                                        unsigned b0, unsigned b1) {
    asm volatile("mma.sync.aligned.m16n8k16.row.col.f32.f16.f16.f32 "
                 "{%0,%1,%2,%3}, {%4,%5,%6,%7}, {%8,%9}, {%0,%1,%2,%3};"
                 : "+f"(d[0]), "+f"(d[1]), "+f"(d[2]), "+f"(d[3])
                 : "r"(a0), "r"(a1), "r"(a2), "r"(a3), "r"(b0), "r"(b1));
}
__device__ __forceinline__ void bar_arrive(int idx) {
    asm volatile("red.release.gpu.global.add.u32 [%0], 1;" :: "l"(&g_bar[idx]) : "memory");
}
__device__ __forceinline__ void poll16(int idx) {   // single acquire load per iteration
    unsigned v;
    do {
        asm volatile("ld.acquire.gpu.global.u32 %0, [%1];" : "=r"(v) : "l"(&g_bar[idx]) : "memory");
    } while (v < 16u);
}
__device__ __forceinline__ void sts_vol(unsigned addr, unsigned v) {
    asm volatile("st.volatile.shared.u32 [%0], %1;" :: "r"(addr), "r"(v) : "memory");
}
__device__ __forceinline__ unsigned lds_vol(unsigned addr) {
    unsigned v;
    asm volatile("ld.volatile.shared.u32 %0, [%1];" : "=r"(v) : "r"(addr) : "memory");
    return v;
}
__device__ __forceinline__ float2 ldcg2(const float* p) {
    return __ldcg(reinterpret_cast<const float2*>(p));
}

// ---------------- single persistent kernel ----------------
__global__ void __launch_bounds__(THREADS, 1)
cornn_persist(const float* __restrict__ x, const float* __restrict__ W,
              const float* __restrict__ bias,
              const float* __restrict__ Wout, const float* __restrict__ bout,
              float* __restrict__ out) {
    __shared__ float Part[KW * 32 * PS];
    __shared__ unsigned s_step;

    const int tid  = threadIdx.x;
    const int cta  = blockIdx.x;
    const int mi   = cta >> 4;            // 0..7
    const int ni   = cta & 15;            // 0..15
    const int lane = tid & 31;
    const int warp = tid >> 5;            // 0..7

    const int rr   = lane >> 2;
    const int cc   = 2 * (lane & 3);
    const unsigned saddr = (unsigned)__cvta_generic_to_shared(&s_step);

    if (tid == 0) sts_vol(saddr, 0u);

    // ================= phase 1: preX[t] = x_t @ W[0:128] + b (per-CTA patches) =================
    {
        unsigned xb0[JPW][4], xb1[JPW][4];
        const int n = ni * 32 + rr;
#pragma unroll
        for (int j = 0; j < JPW; ++j) {
            const int k0 = j * 16 + cc;
#pragma unroll
            for (int nf = 0; nf < 4; ++nf) {
                const float* wp = W + (size_t)k0 * NHID + n + nf * 8;
                xb0[j][nf] = pack_h2(wp[0],        wp[NHID]);
                xb1[j][nf] = pack_h2(wp[8 * NHID], wp[9 * NHID]);
            }
        }
        float bc[4][2];
#pragma unroll
        for (int nf = 0; nf < 4; ++nf) {
            int col = ni * 32 + nf * 8 + cc;
            bc[nf][0] = bias[col];
            bc[nf][1] = bias[col + 1];
        }
        const int arow = mi * 32 + rr;
        for (int i = 0; i < TSTEPS / KW; ++i) {
            const int t = warp + KW * i;
            float acc0[4][4], acc1[4][4];
#pragma unroll
            for (int nf = 0; nf < 4; ++nf) {
                acc0[nf][0] = bc[nf][0]; acc0[nf][1] = bc[nf][1];
                acc0[nf][2] = bc[nf][0]; acc0[nf][3] = bc[nf][1];
                acc1[nf][0] = bc[nf][0]; acc1[nf][1] = bc[nf][1];
                acc1[nf][2] = bc[nf][0]; acc1[nf][3] = bc[nf][1];
            }
            const float* rx = x + ((size_t)t * BSZ + arow) * NIN + cc;
#pragma unroll
            for (int j = 0; j < JPW; ++j) {
                float2 v0l = ldcg2(rx + j * 16),            v0h = ldcg2(rx + j * 16 + 8);
                float2 v1l = ldcg2(rx + 8 * NIN + j * 16),  v1h = ldcg2(rx + 8 * NIN + j * 16 + 8);
                float2 v2l = ldcg2(rx + 16 * NIN + j * 16), v2h = ldcg2(rx + 16 * NIN + j * 16 + 8);
                float2 v3l = ldcg2(rx + 24 * NIN + j * 16), v3h = ldcg2(rx + 24 * NIN + j * 16 + 8);
                unsigned a0l = pack_h2(v0l.x, v0l.y), a0h = pack_h2(v0h.x, v0h.y);
                unsigned a1l = pack_h2(v1l.x, v1l.y), a1h = pack_h2(v1h.x, v1h.y);
                unsigned a2l = pack_h2(v2l.x, v2l.y), a2h = pack_h2(v2h.x, v2h.y);
                unsigned a3l = pack_h2(v3l.x, v3l.y), a3h = pack_h2(v3h.x, v3h.y);
#pragma unroll
                for (int nf = 0; nf < 4; ++nf) {
                    mma_f16(acc0[nf], a0l, a1l, a0h, a1h, xb0[j][nf], xb1[j][nf]);
                    mma_f16(acc1[nf], a2l, a3l, a2h, a3h, xb0[j][nf], xb1[j][nf]);
                }
            }
            float* dst = g_preX + ((size_t)(cta * TSTEPS + t) * 32) * 32;
#pragma unroll
            for (int nf = 0; nf < 4; ++nf) {
                int co = nf * 8 + cc;
                __stcg((float2*)(dst + rr * 32 + co),        make_float2(acc0[nf][0], acc0[nf][1]));
                __stcg((float2*)(dst + (rr + 8) * 32 + co),  make_float2(acc0[nf][2], acc0[nf][3]));
                __stcg((float2*)(dst + (rr + 16) * 32 + co), make_float2(acc1[nf][0], acc1[nf][1]));
                __stcg((float2*)(dst + (rr + 24) * 32 + co), make_float2(acc1[nf][2], acc1[nf][3]));
            }
        }
    }

    // ================= init: zero fp16 state (buffer 0), arrive (t=0) =================
    const int srow = tid >> 3;                 // 0..31
    const int scol = (tid & 7) * 4;            // 0,4,..,28
    const int grow = mi * 32 + srow;
    const int gcol = ni * 32 + scol;
    const int blk  = gcol >> 4;
    const int pp   = (gcol & 15) >> 1;         // 0,2,4,6
    const int pos0 = (pp < 4) ? 2 * pp : 2 * pp - 7;
    const int pos1 = ((pp + 1) < 4) ? 2 * (pp + 1) : 2 * (pp + 1) - 7;
    const int hbase = grow * 256 + blk * 8;

    __stcg(&g_Hz[0][hbase + pos0], 0u);  __stcg(&g_Hz[0][hbase + pos1], 0u);
    __stcg(&g_Hy[0][hbase + pos0], 0u);  __stcg(&g_Hy[0][hbase + pos1], 0u);
    __syncthreads();
    if (tid == 0) bar_arrive(BARIDX(0, mi));

    // ================= main-loop B fragments: W rows 128 + warp*128 .. +128 =================
    unsigned wb0[JPW][4], wb1[JPW][4];
    {
        const int n = ni * 32 + rr;
#pragma unroll
        for (int j = 0; j < JPW; ++j) {
            const int k0 = 128 + warp * 128 + j * 16 + cc;
#pragma unroll
            for (int nf = 0; nf < 4; ++nf) {
                const float* wp = W + (size_t)k0 * NHID + n + nf * 8;
                wb0[j][nf] = pack_h2(wp[0],        wp[NHID]);
                wb1[j][nf] = pack_h2(wp[8 * NHID], wp[9 * NHID]);
            }
        }
    }

    // consumer A-fragment base (R6 layout): slice blocks, lane pair offset 2c
    const int grow0 = mi * 32 + rr;
    const int hoff  = grow0 * 256 + (warp & 3) * 64 + 2 * (lane & 3);

    float hyr[4] = {0, 0, 0, 0}, hzr[4] = {0, 0, 0, 0};

    // ================= recurrence =================
    for (int t = 0; t < TSTEPS; ++t) {
        const int rb = t & 1, wbuf = rb ^ 1;

        // prefetch CTA-private preX patch
        float4 px = __ldcg((const float4*)(g_preX +
                         (((size_t)(cta * TSTEPS + t) * 32 + srow) * 32 + scol)));

        // single global poller; broadcast via smem; warps spin on smem (no L2 traffic)
        if (tid == 0) {
            poll16(BARIDX(t, mi));
            sts_vol(saddr, (unsigned)(t + 1));
        }
        if (lane == 0) {
            while (lds_vol(saddr) < (unsigned)(t + 1)) { }
        }
        __syncwarp();

        const unsigned* hp = ((warp < 4) ? g_Hz[rb] : g_Hy[rb]) + hoff;

        float acc0[4][4], acc1[4][4];
#pragma unroll
        for (int nf = 0; nf < 4; ++nf)
#pragma unroll
            for (int c = 0; c < 4; ++c) { acc0[nf][c] = 0.f; acc1[nf][c] = 0.f; }

#pragma unroll
        for (int j = 0; j < JPW; ++j) {
            const unsigned* q = hp + j * 8;
            uint2 u0 = __ldcg((const uint2*)(q));
            uint2 u1 = __ldcg((const uint2*)(q + 8 * 256));
            uint2 u2 = __ldcg((const uint2*)(q + 16 * 256));
            uint2 u3 = __ldcg((const uint2*)(q + 24 * 256));
#pragma unroll
            for (int nf = 0; nf < 4; ++nf) {
                mma_f16(acc0[nf], u0.x, u1.x, u0.y, u1.y, wb0[j][nf], wb1[j][nf]);
                mma_f16(acc1[nf], u2.x, u3.x, u2.y, u3.y, wb0[j][nf], wb1[j][nf]);
            }
        }

        // write this warp's partial
        {
            float* P = Part + warp * (32 * PS);
#pragma unroll
            for (int nf = 0; nf < 4; ++nf) {
                int co = nf * 8 + cc;
                *(float2*)(P + rr * PS + co)        = make_float2(acc0[nf][0], acc0[nf][1]);
                *(float2*)(P + (rr + 8) * PS + co)  = make_float2(acc0[nf][2], acc0[nf][3]);
                *(float2*)(P + (rr + 16) * PS + co) = make_float2(acc1[nf][0], acc1[nf][1]);
                *(float2*)(P + (rr + 24) * PS + co) = make_float2(acc1[nf][2], acc1[nf][3]);
            }
        }
        __syncthreads();   // all partials in smem

        // reduce 8 partials + preX, tanh, state update, publish fp16 state
        {
            float s0 = px.x, s1 = px.y, s2 = px.z, s3 = px.w;
#pragma unroll
            for (int p = 0; p < KW; ++p) {
                float4 v = *(const float4*)(Part + p * (32 * PS) + srow * PS + scol);
                s0 += v.x; s1 += v.y; s2 += v.z; s3 += v.w;
            }
            float pre0 = fast_tanh(s0);
            float pre1 = fast_tanh(s1);
            float pre2 = fast_tanh(s2);
            float pre3 = fast_tanh(s3);
            hzr[0] += DTc * (pre0 - GAMc * hyr[0] - EPSc * hzr[0]);  hyr[0] += DTc * hzr[0];
            hzr[1] += DTc * (pre1 - GAMc * hyr[1] - EPSc * hzr[1]);  hyr[1] += DTc * hzr[1];
            hzr[2] += DTc * (pre2 - GAMc * hyr[2] - EPSc * hzr[2]);  hyr[2] += DTc * hzr[2];
            hzr[3] += DTc * (pre3 - GAMc * hyr[3] - EPSc * hzr[3]);  hyr[3] += DTc * hzr[3];

            __stcg(&g_Hz[wbuf][hbase + pos0], pack_h2(hzr[0], hzr[1]));
            __stcg(&g_Hz[wbuf][hbase + pos1], pack_h2(hzr[2], hzr[3]));
            __stcg(&g_Hy[wbuf][hbase + pos0], pack_h2(hyr[0], hyr[1]));
            __stcg(&g_Hy[wbuf][hbase + pos1], pack_h2(hyr[2], hyr[3]));
            if (t == TSTEPS - 1) {
                __stcg((float4*)&g_hyf[(size_t)grow * NHID + gcol],
                       make_float4(hyr[0], hyr[1], hyr[2], hyr[3]));
            }
        }
        __syncthreads();   // state stores done CTA-wide; Part reusable
        if (tid == 0) bar_arrive(BARIDX(t + 1, mi));
    }

    // ================= proper final barrier (all 16 producers of rows mi done) =================
    if (tid == 0) poll16(BARIDX(TSTEPS, mi));
    __syncthreads();

    // ---- fused output GEMM: out = hy_final @ Wout + bout ----
    if (warp < 2) {
        int row = cta * 2 + warp;
        const float* h = g_hyf + (size_t)row * NHID;
        float acc[NOUT];
#pragma unroll
        for (int o = 0; o < NOUT; ++o) acc[o] = 0.f;
        for (int k = lane; k < NHID; k += 32) {
            float hv = __ldcg(h + k);
#pragma unroll
            for (int o = 0; o < NOUT; ++o) acc[o] += hv * Wout[k * NOUT + o];
        }
#pragma unroll
        for (int o = 0; o < NOUT; ++o) {
#pragma unroll
            for (int s = 16; s > 0; s >>= 1)
                acc[o] += __shfl_xor_sync(0xffffffffu, acc[o], s);
        }
        if (lane == 0) {
#pragma unroll
            for (int o = 0; o < NOUT; ++o) out[row * NOUT + o] = acc[o] + bout[o];
        }
    }

    // ---- safe self-reset: last arriver of group (after all pollers passed final) ----
    if (tid == 0) {
        unsigned old = atomicAdd(&g_fin[mi], 1u);
        sts_vol(saddr, (old == 15u) ? 0xFFFFFFFFu : 0u);
    }
    __syncthreads();
    if (lds_vol(saddr) == 0xFFFFFFFFu) {       // last CTA of group resets in parallel
        for (int tt = tid; tt <= TSTEPS; tt += THREADS)
            g_bar[BARIDX(tt, mi)] = 0u;
        __syncthreads();
        if (tid == 0) {
            __threadfence();
            g_fin[mi] = 0u;
        }
    }
}

// ---------------- launch ----------------
extern "C" void kernel_launch(void* const* d_in, const int* in_sizes, int n_in,
                              void* d_out, int out_size) {
    (void)in_sizes; (void)n_in; (void)out_size;
    const float* x    = (const float*)d_in[0];
    const float* W    = (const float*)d_in[1];
    const float* b    = (const float*)d_in[2];
    const float* Wout = (const float*)d_in[3];
    const float* bout = (const float*)d_in[4];
    float* out = (float*)d_out;

    cornn_persist<<<NCTA, THREADS>>>(x, W, b, Wout, bout, out);
}